// round 1
// baseline (speedup 1.0000x reference)
#include <cuda_runtime.h>
#include <math.h>

// ---------------------------------------------------------------------------
// EMLLA block: LN -> {in-proj, act-proj(silu)} -> dwconv+silu -> qk-proj(elu+1)
//              -> linear attention (kv 32x32 per head) -> lepe dwconv
//              -> (att+lepe)*act_res @ out_w + out_b + shortcut
// B=16, H=W=56 (L=3136), C=192, 6 heads x 32 dims.
// ---------------------------------------------------------------------------

constexpr int Himg = 56, Wimg = 56, Lseq = 3136, Cdim = 192;
constexpr int NHEAD = 6, HDIM = 32, BATCH = 16;
constexpr int BL = BATCH * Lseq;              // 50176 rows
constexpr float LN_EPS = 1e-5f;

// Scratch (device globals: allocation-free, graph-capture safe)
__device__ float g_xn [(size_t)BL * Cdim];        // xn, later reused for g = (att+lepe)*act_res
__device__ float g_act[(size_t)BL * Cdim];        // silu(xn@act_w+b)
__device__ float g_h0 [(size_t)BL * Cdim];        // in-proj result, later reused for att
__device__ float g_h  [(size_t)BL * Cdim];        // silu(dwconv(h0))
__device__ float g_qk [(size_t)BL * 2 * Cdim];    // elu(h@qk_w+b)+1
__device__ float g_kv [BATCH * NHEAD * HDIM * HDIM];
__device__ float g_km [BATCH * NHEAD * HDIM];

// ---------------------------------------------------------------------------
// LayerNorm: one warp per row of 192, 6 elems/lane
// ---------------------------------------------------------------------------
__global__ void ln_kernel(const float* __restrict__ x, const float* __restrict__ gamma,
                          const float* __restrict__ beta, float* __restrict__ out) {
    int row  = blockIdx.x * 8 + (threadIdx.x >> 5);
    int lane = threadIdx.x & 31;
    const float* xr = x + (size_t)row * Cdim;
    float v[6]; float s = 0.f, ss = 0.f;
#pragma unroll
    for (int i = 0; i < 6; i++) { v[i] = xr[lane + 32 * i]; s += v[i]; ss += v[i] * v[i]; }
#pragma unroll
    for (int o = 16; o > 0; o >>= 1) {
        s  += __shfl_xor_sync(0xffffffffu, s,  o);
        ss += __shfl_xor_sync(0xffffffffu, ss, o);
    }
    float mu   = s * (1.f / Cdim);
    float var  = ss * (1.f / Cdim) - mu * mu;
    float rstd = rsqrtf(var + LN_EPS);
    float* orow = out + (size_t)row * Cdim;
#pragma unroll
    for (int i = 0; i < 6; i++) {
        int c = lane + 32 * i;
        orow[c] = (v[i] - mu) * rstd * gamma[c] + beta[c];
    }
}

// ---------------------------------------------------------------------------
// fp32 tiled GEMM: Y[M,N] = A[M,K] @ W[K,N] + bias (+ activation) (+ residual)
// BM=BN=64, BK=16, 256 threads, 4x4 microtile. M%64==0, N%64==0, K%16==0.
// ACT: 0=none, 1=silu, 2=elu+1
// ---------------------------------------------------------------------------
template <int ACT>
__global__ __launch_bounds__(256) void gemm_kernel(
    const float* __restrict__ A, const float* __restrict__ Wt,
    const float* __restrict__ bias, const float* __restrict__ resid,
    float* __restrict__ Y, int M, int N, int K)
{
    constexpr int BM = 64, BN = 64, BK = 16;
    __shared__ float As[BK][BM + 1];
    __shared__ float Bs[BK][BN];
    int tid = threadIdx.x;
    int bm = blockIdx.y * BM, bn = blockIdx.x * BN;
    int arow = tid >> 2,  acol = (tid & 3) * 4;
    int brow = tid >> 4,  bcol = (tid & 15) * 4;
    int ty = tid >> 4,    tx = tid & 15;
    float acc[4][4] = {};
    const float* Ap = A  + (size_t)(bm + arow) * K + acol;
    const float* Bp = Wt + (size_t)brow * N + bn + bcol;

    for (int k0 = 0; k0 < K; k0 += BK) {
        float4 av = *(const float4*)(Ap + k0);
        As[acol + 0][arow] = av.x;
        As[acol + 1][arow] = av.y;
        As[acol + 2][arow] = av.z;
        As[acol + 3][arow] = av.w;
        float4 bv = *(const float4*)(Bp + (size_t)k0 * N);
        *(float4*)&Bs[brow][bcol] = bv;
        __syncthreads();
#pragma unroll
        for (int kk = 0; kk < BK; kk++) {
            float a[4], b[4];
#pragma unroll
            for (int i = 0; i < 4; i++) a[i] = As[kk][ty * 4 + i];
#pragma unroll
            for (int j = 0; j < 4; j++) b[j] = Bs[kk][tx * 4 + j];
#pragma unroll
            for (int i = 0; i < 4; i++)
#pragma unroll
                for (int j = 0; j < 4; j++) acc[i][j] = fmaf(a[i], b[j], acc[i][j]);
        }
        __syncthreads();
    }

#pragma unroll
    for (int i = 0; i < 4; i++) {
        int m = bm + ty * 4 + i;
        float* yr = Y + (size_t)m * N + bn + tx * 4;
        const float* rr = resid ? resid + (size_t)m * N + bn + tx * 4 : nullptr;
#pragma unroll
        for (int j = 0; j < 4; j++) {
            float vv = acc[i][j] + bias[bn + tx * 4 + j];
            if (ACT == 1)      vv = vv / (1.f + expf(-vv));                 // silu
            else if (ACT == 2) vv = (vv > 0.f) ? vv + 1.f : expf(vv);       // elu+1
            if (rr) vv += rr[j];
            yr[j] = vv;
        }
    }
}

// ---------------------------------------------------------------------------
// Depthwise 3x3 SAME conv + silu. One block per pixel, one thread per channel.
// ---------------------------------------------------------------------------
__global__ void dwconv_silu_kernel(const float* __restrict__ in, const float* __restrict__ w,
                                   const float* __restrict__ bias, float* __restrict__ out)
{
    int pix = blockIdx.x;
    int c   = threadIdx.x;
    int b   = pix / (Himg * Wimg);
    int rem = pix - b * Himg * Wimg;
    int y = rem / Wimg, x = rem - y * Wimg;
    float acc = bias[c];
#pragma unroll
    for (int dy = 0; dy < 3; dy++) {
        int yy = y + dy - 1; if (yy < 0 || yy >= Himg) continue;
#pragma unroll
        for (int dx = 0; dx < 3; dx++) {
            int xx = x + dx - 1; if (xx < 0 || xx >= Wimg) continue;
            acc = fmaf(in[((size_t)(b * Himg + yy) * Wimg + xx) * Cdim + c],
                       w[(dy * 3 + dx) * Cdim + c], acc);
        }
    }
    out[(size_t)pix * Cdim + c] = acc / (1.f + expf(-acc));
}

// Fused: g = (att + dwconv(h)+lepe_b) * act_res
__global__ void lepe_mul_kernel(const float* __restrict__ hin, const float* __restrict__ w,
                                const float* __restrict__ bias, const float* __restrict__ att,
                                const float* __restrict__ actres, float* __restrict__ out)
{
    int pix = blockIdx.x;
    int c   = threadIdx.x;
    int b   = pix / (Himg * Wimg);
    int rem = pix - b * Himg * Wimg;
    int y = rem / Wimg, x = rem - y * Wimg;
    float acc = bias[c];
#pragma unroll
    for (int dy = 0; dy < 3; dy++) {
        int yy = y + dy - 1; if (yy < 0 || yy >= Himg) continue;
#pragma unroll
        for (int dx = 0; dx < 3; dx++) {
            int xx = x + dx - 1; if (xx < 0 || xx >= Wimg) continue;
            acc = fmaf(hin[((size_t)(b * Himg + yy) * Wimg + xx) * Cdim + c],
                       w[(dy * 3 + dx) * Cdim + c], acc);
        }
    }
    size_t idx = (size_t)pix * Cdim + c;
    out[idx] = (att[idx] + acc) * actres[idx];
}

// ---------------------------------------------------------------------------
// kv[b,h] = k^T v / L  (32x32), kmean[b,h] = mean_n k  -- one block per (b,h)
// Lane d of a warp holds k[n,d]; 32 shuffles broadcast v[n,e].
// ---------------------------------------------------------------------------
__global__ void kv_kernel(const float* __restrict__ qk, const float* __restrict__ hv,
                          float* __restrict__ kv, float* __restrict__ km)
{
    int bh = blockIdx.x;
    int b = bh / NHEAD, hd = bh % NHEAD;
    __shared__ float skv[HDIM * HDIM];
    __shared__ float skm[HDIM];
    int tid = threadIdx.x;
    for (int i = tid; i < HDIM * HDIM; i += blockDim.x) skv[i] = 0.f;
    if (tid < HDIM) skm[tid] = 0.f;
    __syncthreads();

    int lane = tid & 31, warp = tid >> 5;   // 8 warps
    float acc[HDIM];
#pragma unroll
    for (int e = 0; e < HDIM; e++) acc[e] = 0.f;
    float acck = 0.f;

    for (int n = warp; n < Lseq; n += 8) {
        size_t rowq = (size_t)(b * Lseq + n) * (2 * Cdim);
        float kd = qk[rowq + Cdim + hd * HDIM + lane];            // k half
        float ve = hv[(size_t)(b * Lseq + n) * Cdim + hd * HDIM + lane];  // v = h
        acck += kd;
#pragma unroll
        for (int e = 0; e < HDIM; e++)
            acc[e] = fmaf(kd, __shfl_sync(0xffffffffu, ve, e), acc[e]);
    }
#pragma unroll
    for (int e = 0; e < HDIM; e++) atomicAdd(&skv[lane * HDIM + e], acc[e]);
    atomicAdd(&skm[lane], acck);
    __syncthreads();

    const float invL = 1.f / (float)Lseq;
    for (int i = tid; i < HDIM * HDIM; i += blockDim.x)
        kv[(size_t)bh * HDIM * HDIM + i] = skv[i] * invL;
    if (tid < HDIM) km[bh * HDIM + tid] = skm[tid] * invL;
}

// ---------------------------------------------------------------------------
// att[n, h*32+e] = z * sum_d q[n,d]*kv[d,e];  z = 1/(q . kmean + 1e-6)
// grid (B*NH, 8); one warp per token.
// ---------------------------------------------------------------------------
__global__ void att_kernel(const float* __restrict__ qk, const float* __restrict__ kv,
                           const float* __restrict__ km, float* __restrict__ att)
{
    int bh = blockIdx.x;
    int b = bh / NHEAD, hd = bh % NHEAD;
    __shared__ float skv[HDIM * HDIM];
    __shared__ float skm[HDIM];
    int tid = threadIdx.x;
    for (int i = tid; i < HDIM * HDIM; i += blockDim.x)
        skv[i] = kv[(size_t)bh * HDIM * HDIM + i];
    if (tid < HDIM) skm[tid] = km[bh * HDIM + tid];
    __syncthreads();

    int lane = tid & 31, warp = tid >> 5;        // 8 warps
    const int per = Lseq / 8;                    // gridDim.y == 8 -> 392
    int n0 = blockIdx.y * per;
    for (int n = n0 + warp; n < n0 + per; n += 8) {
        float qe = qk[(size_t)(b * Lseq + n) * (2 * Cdim) + hd * HDIM + lane];  // q half
        float p = qe * skm[lane];
#pragma unroll
        for (int o = 16; o > 0; o >>= 1) p += __shfl_xor_sync(0xffffffffu, p, o);
        float z = 1.f / (p + 1e-6f);
        float a = 0.f;
#pragma unroll
        for (int d = 0; d < HDIM; d++)
            a = fmaf(__shfl_sync(0xffffffffu, qe, d), skv[d * HDIM + lane], a);
        att[(size_t)(b * Lseq + n) * Cdim + hd * HDIM + lane] = a * z;
    }
}

// ---------------------------------------------------------------------------
extern "C" void kernel_launch(void* const* d_in, const int* in_sizes, int n_in,
                              void* d_out, int out_size)
{
    const float* x      = (const float*)d_in[0];
    const float* norm_g = (const float*)d_in[1];
    const float* norm_b = (const float*)d_in[2];
    const float* in_w   = (const float*)d_in[3];
    const float* in_b   = (const float*)d_in[4];
    const float* act_w  = (const float*)d_in[5];
    const float* act_b  = (const float*)d_in[6];
    const float* dwc_w  = (const float*)d_in[7];
    const float* dwc_b  = (const float*)d_in[8];
    const float* qk_w   = (const float*)d_in[9];
    const float* qk_b   = (const float*)d_in[10];
    const float* lepe_w = (const float*)d_in[11];
    const float* lepe_b = (const float*)d_in[12];
    const float* out_w  = (const float*)d_in[13];
    const float* out_b  = (const float*)d_in[14];
    float* out = (float*)d_out;

    float *xn, *act, *h0, *h, *qk, *kv, *km;
    cudaGetSymbolAddress((void**)&xn,  g_xn);
    cudaGetSymbolAddress((void**)&act, g_act);
    cudaGetSymbolAddress((void**)&h0,  g_h0);
    cudaGetSymbolAddress((void**)&h,   g_h);
    cudaGetSymbolAddress((void**)&qk,  g_qk);
    cudaGetSymbolAddress((void**)&kv,  g_kv);
    cudaGetSymbolAddress((void**)&km,  g_km);

    // 1) LayerNorm
    ln_kernel<<<BL / 8, 256>>>(x, norm_g, norm_b, xn);

    // 2) in-proj (no act) and act-proj (silu)
    dim3 gC(Cdim / 64, BL / 64);
    gemm_kernel<0><<<gC, 256>>>(xn, in_w,  in_b,  nullptr, h0,  BL, Cdim, Cdim);
    gemm_kernel<1><<<gC, 256>>>(xn, act_w, act_b, nullptr, act, BL, Cdim, Cdim);

    // 3) dwconv + silu -> h
    dwconv_silu_kernel<<<BL, Cdim>>>(h0, dwc_w, dwc_b, h);

    // 4) qk-proj with elu+1 epilogue
    dim3 gQK(2 * Cdim / 64, BL / 64);
    gemm_kernel<2><<<gQK, 256>>>(h, qk_w, qk_b, nullptr, qk, BL, 2 * Cdim, Cdim);

    // 5) linear attention
    kv_kernel<<<BATCH * NHEAD, 256>>>(qk, h, kv, km);
    att_kernel<<<dim3(BATCH * NHEAD, 8), 256>>>(qk, kv, km, h0);   // att -> h0

    // 6) g = (att + lepe) * act_res  -> xn (reuse)
    lepe_mul_kernel<<<BL, Cdim>>>(h, lepe_w, lepe_b, h0, act, xn);

    // 7) out-proj + bias + shortcut
    gemm_kernel<0><<<gC, 256>>>(xn, out_w, out_b, x, out, BL, Cdim, Cdim);
}

// round 3
// speedup vs baseline: 1.6951x; 1.6951x over previous
#include <cuda_runtime.h>
#include <cuda_bf16.h>
#include <stdint.h>
#include <math.h>

// ---------------------------------------------------------------------------
// EMLLA block, bf16 tensor-core GEMMs (mma.sync m16n8k16, fp32 accumulate).
// B=16, H=W=56 (L=3136), C=192, 6 heads x 32 dims.
// ---------------------------------------------------------------------------

constexpr int Himg = 56, Wimg = 56, Lseq = 3136, Cdim = 192;
constexpr int NHEAD = 6, HDIM = 32, BATCH = 16;
constexpr int BL = BATCH * Lseq;              // 50176 rows
constexpr float LN_EPS = 1e-5f;

// Scratch (device globals: allocation-free, graph-capture safe)
__device__ float g_xn [(size_t)BL * Cdim];
__device__ float g_act[(size_t)BL * Cdim];
__device__ float g_h0 [(size_t)BL * Cdim];
__device__ float g_h  [(size_t)BL * Cdim];
__device__ float g_qk [(size_t)BL * 2 * Cdim];
__device__ float g_kv [BATCH * NHEAD * HDIM * HDIM];
__device__ float g_km [BATCH * NHEAD * HDIM];

// ---------------------------------------------------------------------------
// helpers
// ---------------------------------------------------------------------------
__device__ __forceinline__ uint32_t smem_u32(const void* p) {
    return (uint32_t)__cvta_generic_to_shared(p);
}
__device__ __forceinline__ uint32_t packbf(float a, float b) {
    __nv_bfloat162 v = __floats2bfloat162_rn(a, b);
    return *reinterpret_cast<uint32_t*>(&v);
}
__device__ __forceinline__ void ldm_x4(uint32_t& r0, uint32_t& r1, uint32_t& r2,
                                       uint32_t& r3, uint32_t a) {
    asm volatile("ldmatrix.sync.aligned.m8n8.x4.shared.b16 {%0,%1,%2,%3}, [%4];"
                 : "=r"(r0), "=r"(r1), "=r"(r2), "=r"(r3) : "r"(a));
}
__device__ __forceinline__ void ldm_x4t(uint32_t& r0, uint32_t& r1, uint32_t& r2,
                                        uint32_t& r3, uint32_t a) {
    asm volatile("ldmatrix.sync.aligned.m8n8.x4.trans.shared.b16 {%0,%1,%2,%3}, [%4];"
                 : "=r"(r0), "=r"(r1), "=r"(r2), "=r"(r3) : "r"(a));
}
__device__ __forceinline__ void mma16816(float* c, uint32_t a0, uint32_t a1,
                                         uint32_t a2, uint32_t a3,
                                         uint32_t b0, uint32_t b1) {
    asm volatile(
        "mma.sync.aligned.m16n8k16.row.col.f32.bf16.bf16.f32 "
        "{%0,%1,%2,%3}, {%4,%5,%6,%7}, {%8,%9}, {%0,%1,%2,%3};"
        : "+f"(c[0]), "+f"(c[1]), "+f"(c[2]), "+f"(c[3])
        : "r"(a0), "r"(a1), "r"(a2), "r"(a3), "r"(b0), "r"(b1));
}

// ---------------------------------------------------------------------------
// LayerNorm: one warp per row of 192
// ---------------------------------------------------------------------------
__global__ void ln_kernel(const float* __restrict__ x, const float* __restrict__ gamma,
                          const float* __restrict__ beta, float* __restrict__ out) {
    int row  = blockIdx.x * 8 + (threadIdx.x >> 5);
    int lane = threadIdx.x & 31;
    const float* xr = x + (size_t)row * Cdim;
    float v[6]; float s = 0.f, ss = 0.f;
#pragma unroll
    for (int i = 0; i < 6; i++) { v[i] = xr[lane + 32 * i]; s += v[i]; ss += v[i] * v[i]; }
#pragma unroll
    for (int o = 16; o > 0; o >>= 1) {
        s  += __shfl_xor_sync(0xffffffffu, s,  o);
        ss += __shfl_xor_sync(0xffffffffu, ss, o);
    }
    float mu   = s * (1.f / Cdim);
    float var  = ss * (1.f / Cdim) - mu * mu;
    float rstd = rsqrtf(var + LN_EPS);
    float* orow = out + (size_t)row * Cdim;
#pragma unroll
    for (int i = 0; i < 6; i++) {
        int c = lane + 32 * i;
        orow[c] = (v[i] - mu) * rstd * gamma[c] + beta[c];
    }
}

// ---------------------------------------------------------------------------
// bf16 tensor-core GEMM: Y[M,N] = A[M,K] @ W[K,N] + bias (+act) (+resid)
// BM=128, BN=64, BK=32, 8 warps (4x2), warp tile 32x32 via m16n8k16.
// ACT: 0=none, 1=silu, 2=elu+1.  M%128==0, N%64==0, K%32==0.
// ---------------------------------------------------------------------------
template <int ACT, bool RES>
__global__ __launch_bounds__(256) void gemm_bf16(
    const float* __restrict__ A, const float* __restrict__ W,
    const float* __restrict__ bias, const float* __restrict__ resid,
    float* __restrict__ Y, int M, int N, int K)
{
    constexpr int BM = 128, BN = 64, BK = 32;
    constexpr int ASTR = 40;   // bf16 elems per A smem row (80B, conflict-free ldmatrix)
    constexpr int BSTR = 72;   // bf16 elems per B smem row (144B)
    __shared__ __align__(16) uint32_t As[BM * ASTR / 2];   // 10240 B
    __shared__ __align__(16) uint32_t Bs[BK * BSTR / 2];   //  4608 B

    int tid  = threadIdx.x;
    int bm   = blockIdx.y * BM, bn = blockIdx.x * BN;
    int warp = tid >> 5, lane = tid & 31;
    int wm   = (warp & 3) * 32, wn = (warp >> 2) * 32;

    // global staging assignment
    int arow = tid >> 1,  acol = (tid & 1) * 16;   // 16 floats per thread
    int brow = tid >> 3,  bcol = (tid & 7) * 8;    // 8 floats per thread
    const float* Ap = A + (size_t)(bm + arow) * K + acol;
    const float* Wp = W + (size_t)brow * N + bn + bcol;

    float acc[2][4][4];
#pragma unroll
    for (int i = 0; i < 2; i++)
#pragma unroll
        for (int j = 0; j < 4; j++)
#pragma unroll
            for (int l = 0; l < 4; l++) acc[i][j][l] = 0.f;

    uint32_t as_base = smem_u32(As);
    uint32_t bs_base = smem_u32(Bs);
    int a_row = wm + (lane & 7) + ((lane >> 3) & 1) * 8;
    int a_col = (lane >> 4) * 8;
    int b_k   = (lane & 7) + ((lane >> 3) & 1) * 8;
    int b_n   = wn + (lane >> 4) * 8;

    const int KT = K / BK;
    float4 ar[4], br[2];
    // prefetch tile 0
#pragma unroll
    for (int i = 0; i < 4; i++) ar[i] = *(const float4*)(Ap + i * 4);
#pragma unroll
    for (int i = 0; i < 2; i++) br[i] = *(const float4*)(Wp + i * 4);

    for (int kt = 0; kt < KT; kt++) {
        // store staged tile to smem (fp32 -> bf16)
        uint32_t* ad = &As[arow * (ASTR / 2) + acol / 2];
#pragma unroll
        for (int i = 0; i < 4; i++) {
            ad[2 * i + 0] = packbf(ar[i].x, ar[i].y);
            ad[2 * i + 1] = packbf(ar[i].z, ar[i].w);
        }
        uint32_t* bd = &Bs[brow * (BSTR / 2) + bcol / 2];
        bd[0] = packbf(br[0].x, br[0].y);
        bd[1] = packbf(br[0].z, br[0].w);
        bd[2] = packbf(br[1].x, br[1].y);
        bd[3] = packbf(br[1].z, br[1].w);
        __syncthreads();

        if (kt + 1 < KT) {
            const float* Apn = Ap + (kt + 1) * BK;
            const float* Wpn = Wp + (size_t)(kt + 1) * BK * N;
#pragma unroll
            for (int i = 0; i < 4; i++) ar[i] = *(const float4*)(Apn + i * 4);
#pragma unroll
            for (int i = 0; i < 2; i++) br[i] = *(const float4*)(Wpn + i * 4);
        }

#pragma unroll
        for (int ks = 0; ks < 2; ks++) {
            uint32_t afr[2][4];
#pragma unroll
            for (int mt = 0; mt < 2; mt++) {
                uint32_t addr = as_base +
                    ((a_row + mt * 16) * ASTR + (a_col + ks * 16)) * 2;
                ldm_x4(afr[mt][0], afr[mt][1], afr[mt][2], afr[mt][3], addr);
            }
            uint32_t bfr[4][2];
#pragma unroll
            for (int p = 0; p < 2; p++) {
                uint32_t addr = bs_base +
                    ((b_k + ks * 16) * BSTR + (b_n + p * 16)) * 2;
                uint32_t r0, r1, r2, r3;
                ldm_x4t(r0, r1, r2, r3, addr);
                bfr[p * 2 + 0][0] = r0; bfr[p * 2 + 0][1] = r1;
                bfr[p * 2 + 1][0] = r2; bfr[p * 2 + 1][1] = r3;
            }
#pragma unroll
            for (int mt = 0; mt < 2; mt++)
#pragma unroll
                for (int nt = 0; nt < 4; nt++)
                    mma16816(acc[mt][nt], afr[mt][0], afr[mt][1], afr[mt][2],
                             afr[mt][3], bfr[nt][0], bfr[nt][1]);
        }
        __syncthreads();
    }

    // epilogue
    int r0 = lane >> 2, c0 = (lane & 3) * 2;
#pragma unroll
    for (int mt = 0; mt < 2; mt++) {
#pragma unroll
        for (int half = 0; half < 2; half++) {
            int row = bm + wm + mt * 16 + r0 + half * 8;
#pragma unroll
            for (int nt = 0; nt < 4; nt++) {
                int col = bn + wn + nt * 8 + c0;
                float v0 = acc[mt][nt][half * 2 + 0] + bias[col];
                float v1 = acc[mt][nt][half * 2 + 1] + bias[col + 1];
                if (ACT == 1) {
                    v0 = v0 / (1.f + expf(-v0));
                    v1 = v1 / (1.f + expf(-v1));
                } else if (ACT == 2) {
                    v0 = (v0 > 0.f) ? v0 + 1.f : expf(v0);
                    v1 = (v1 > 0.f) ? v1 + 1.f : expf(v1);
                }
                if (RES) {
                    const float* rr = resid + (size_t)row * N + col;
                    v0 += rr[0]; v1 += rr[1];
                }
                float2 o; o.x = v0; o.y = v1;
                *(float2*)&Y[(size_t)row * N + col] = o;
            }
        }
    }
}

// ---------------------------------------------------------------------------
// Depthwise 3x3 SAME conv + silu: 4 vertical pixels per thread.
// grid = BATCH * (Himg/4) * Wimg, block = Cdim
// ---------------------------------------------------------------------------
__global__ void dwconv_silu_kernel(const float* __restrict__ in, const float* __restrict__ w,
                                   const float* __restrict__ bias, float* __restrict__ out)
{
    int blk = blockIdx.x;
    int c   = threadIdx.x;
    int x   = blk % Wimg;
    int t   = blk / Wimg;
    int y4  = t % (Himg / 4);
    int b   = t / (Himg / 4);
    int y0  = y4 * 4;

    float wv[9];
#pragma unroll
    for (int i = 0; i < 9; i++) wv[i] = w[i * Cdim + c];
    float bb = bias[c];
    float acc[4] = {bb, bb, bb, bb};

#pragma unroll
    for (int dx = 0; dx < 3; dx++) {
        int xx = x + dx - 1;
        if (xx < 0 || xx >= Wimg) continue;
#pragma unroll
        for (int ry = -1; ry < 5; ry++) {
            int yy = y0 + ry;
            if (yy < 0 || yy >= Himg) continue;
            float v = in[((size_t)(b * Himg + yy) * Wimg + xx) * Cdim + c];
#pragma unroll
            for (int oy = 0; oy < 4; oy++) {
                int dy = ry - oy + 1;
                if (dy >= 0 && dy < 3) acc[oy] = fmaf(v, wv[dy * 3 + dx], acc[oy]);
            }
        }
    }
#pragma unroll
    for (int oy = 0; oy < 4; oy++) {
        float a = acc[oy];
        out[((size_t)(b * Himg + y0 + oy) * Wimg + x) * Cdim + c] =
            a / (1.f + expf(-a));
    }
}

// Fused: g = (att + dwconv(h)+lepe_b) * act_res, 4 vertical pixels per thread
__global__ void lepe_mul_kernel(const float* __restrict__ hin, const float* __restrict__ w,
                                const float* __restrict__ bias, const float* __restrict__ att,
                                const float* __restrict__ actres, float* __restrict__ out)
{
    int blk = blockIdx.x;
    int c   = threadIdx.x;
    int x   = blk % Wimg;
    int t   = blk / Wimg;
    int y4  = t % (Himg / 4);
    int b   = t / (Himg / 4);
    int y0  = y4 * 4;

    float wv[9];
#pragma unroll
    for (int i = 0; i < 9; i++) wv[i] = w[i * Cdim + c];
    float bb = bias[c];
    float acc[4] = {bb, bb, bb, bb};

#pragma unroll
    for (int dx = 0; dx < 3; dx++) {
        int xx = x + dx - 1;
        if (xx < 0 || xx >= Wimg) continue;
#pragma unroll
        for (int ry = -1; ry < 5; ry++) {
            int yy = y0 + ry;
            if (yy < 0 || yy >= Himg) continue;
            float v = hin[((size_t)(b * Himg + yy) * Wimg + xx) * Cdim + c];
#pragma unroll
            for (int oy = 0; oy < 4; oy++) {
                int dy = ry - oy + 1;
                if (dy >= 0 && dy < 3) acc[oy] = fmaf(v, wv[dy * 3 + dx], acc[oy]);
            }
        }
    }
#pragma unroll
    for (int oy = 0; oy < 4; oy++) {
        size_t idx = ((size_t)(b * Himg + y0 + oy) * Wimg + x) * Cdim + c;
        out[idx] = (att[idx] + acc[oy]) * actres[idx];
    }
}

// ---------------------------------------------------------------------------
// kv[b,h] = k^T v / L  (32x32), kmean = mean_n k
// ---------------------------------------------------------------------------
__global__ void kv_kernel(const float* __restrict__ qk, const float* __restrict__ hv,
                          float* __restrict__ kv, float* __restrict__ km)
{
    int bh = blockIdx.x;
    int b = bh / NHEAD, hd = bh % NHEAD;
    __shared__ float skv[HDIM * HDIM];
    __shared__ float skm[HDIM];
    int tid = threadIdx.x;
    for (int i = tid; i < HDIM * HDIM; i += blockDim.x) skv[i] = 0.f;
    if (tid < HDIM) skm[tid] = 0.f;
    __syncthreads();

    int lane = tid & 31, warp = tid >> 5;
    float acc[HDIM];
#pragma unroll
    for (int e = 0; e < HDIM; e++) acc[e] = 0.f;
    float acck = 0.f;

    for (int n = warp; n < Lseq; n += 8) {
        size_t rowq = (size_t)(b * Lseq + n) * (2 * Cdim);
        float kd = qk[rowq + Cdim + hd * HDIM + lane];
        float ve = hv[(size_t)(b * Lseq + n) * Cdim + hd * HDIM + lane];
        acck += kd;
#pragma unroll
        for (int e = 0; e < HDIM; e++)
            acc[e] = fmaf(kd, __shfl_sync(0xffffffffu, ve, e), acc[e]);
    }
#pragma unroll
    for (int e = 0; e < HDIM; e++) atomicAdd(&skv[lane * HDIM + e], acc[e]);
    atomicAdd(&skm[lane], acck);
    __syncthreads();

    const float invL = 1.f / (float)Lseq;
    for (int i = tid; i < HDIM * HDIM; i += blockDim.x)
        kv[(size_t)bh * HDIM * HDIM + i] = skv[i] * invL;
    if (tid < HDIM) km[bh * HDIM + tid] = skm[tid] * invL;
}

// ---------------------------------------------------------------------------
// att[n, h*32+e] = z * sum_d q[n,d]*kv[d,e];  z = 1/(q.kmean + 1e-6)
// ---------------------------------------------------------------------------
__global__ void att_kernel(const float* __restrict__ qk, const float* __restrict__ kv,
                           const float* __restrict__ km, float* __restrict__ att)
{
    int bh = blockIdx.x;
    int b = bh / NHEAD, hd = bh % NHEAD;
    __shared__ float skv[HDIM * HDIM];
    __shared__ float skm[HDIM];
    int tid = threadIdx.x;
    for (int i = tid; i < HDIM * HDIM; i += blockDim.x)
        skv[i] = kv[(size_t)bh * HDIM * HDIM + i];
    if (tid < HDIM) skm[tid] = km[bh * HDIM + tid];
    __syncthreads();

    int lane = tid & 31, warp = tid >> 5;
    const int per = Lseq / 8;
    int n0 = blockIdx.y * per;
    for (int n = n0 + warp; n < n0 + per; n += 8) {
        float qe = qk[(size_t)(b * Lseq + n) * (2 * Cdim) + hd * HDIM + lane];
        float p = qe * skm[lane];
#pragma unroll
        for (int o = 16; o > 0; o >>= 1) p += __shfl_xor_sync(0xffffffffu, p, o);
        float z = 1.f / (p + 1e-6f);
        float a = 0.f;
#pragma unroll
        for (int d = 0; d < HDIM; d++)
            a = fmaf(__shfl_sync(0xffffffffu, qe, d), skv[d * HDIM + lane], a);
        att[(size_t)(b * Lseq + n) * Cdim + hd * HDIM + lane] = a * z;
    }
}

// ---------------------------------------------------------------------------
extern "C" void kernel_launch(void* const* d_in, const int* in_sizes, int n_in,
                              void* d_out, int out_size)
{
    const float* x      = (const float*)d_in[0];
    const float* norm_g = (const float*)d_in[1];
    const float* norm_b = (const float*)d_in[2];
    const float* in_w   = (const float*)d_in[3];
    const float* in_b   = (const float*)d_in[4];
    const float* act_w  = (const float*)d_in[5];
    const float* act_b  = (const float*)d_in[6];
    const float* dwc_w  = (const float*)d_in[7];
    const float* dwc_b  = (const float*)d_in[8];
    const float* qk_w   = (const float*)d_in[9];
    const float* qk_b   = (const float*)d_in[10];
    const float* lepe_w = (const float*)d_in[11];
    const float* lepe_b = (const float*)d_in[12];
    const float* out_w  = (const float*)d_in[13];
    const float* out_b  = (const float*)d_in[14];
    float* out = (float*)d_out;

    float *xn, *act, *h0, *h, *qk, *kv, *km;
    cudaGetSymbolAddress((void**)&xn,  g_xn);
    cudaGetSymbolAddress((void**)&act, g_act);
    cudaGetSymbolAddress((void**)&h0,  g_h0);
    cudaGetSymbolAddress((void**)&h,   g_h);
    cudaGetSymbolAddress((void**)&qk,  g_qk);
    cudaGetSymbolAddress((void**)&kv,  g_kv);
    cudaGetSymbolAddress((void**)&km,  g_km);

    // 1) LayerNorm
    ln_kernel<<<BL / 8, 256>>>(x, norm_g, norm_b, xn);

    // 2) in-proj (none) and act-proj (silu)
    dim3 gC(Cdim / 64, BL / 128);
    gemm_bf16<0, false><<<gC, 256>>>(xn, in_w,  in_b,  nullptr, h0,  BL, Cdim, Cdim);
    gemm_bf16<1, false><<<gC, 256>>>(xn, act_w, act_b, nullptr, act, BL, Cdim, Cdim);

    // 3) dwconv + silu -> h
    int dwgrid = BATCH * (Himg / 4) * Wimg;
    dwconv_silu_kernel<<<dwgrid, Cdim>>>(h0, dwc_w, dwc_b, h);

    // 4) qk-proj with elu+1 epilogue
    dim3 gQK(2 * Cdim / 64, BL / 128);
    gemm_bf16<2, false><<<gQK, 256>>>(h, qk_w, qk_b, nullptr, qk, BL, 2 * Cdim, Cdim);

    // 5) linear attention
    kv_kernel<<<BATCH * NHEAD, 256>>>(qk, h, kv, km);
    att_kernel<<<dim3(BATCH * NHEAD, 8), 256>>>(qk, kv, km, h0);   // att -> h0

    // 6) g = (att + lepe) * act_res  -> xn (reuse)
    lepe_mul_kernel<<<dwgrid, Cdim>>>(h, lepe_w, lepe_b, h0, act, xn);

    // 7) out-proj + bias + shortcut
    gemm_bf16<0, true><<<gC, 256>>>(xn, out_w, out_b, x, out, BL, Cdim, Cdim);
}

// round 4
// speedup vs baseline: 2.4839x; 1.4653x over previous
#include <cuda_runtime.h>
#include <cuda_bf16.h>
#include <stdint.h>
#include <math.h>

// ---------------------------------------------------------------------------
// EMLLA block, bf16 end-to-end: bf16 intermediates + cp.async double-buffered
// HMMA GEMMs (m16n8k16, fp32 accum). B=16, H=W=56, C=192, 6 heads x 32.
// ---------------------------------------------------------------------------

constexpr int Himg = 56, Wimg = 56, Lseq = 3136, Cdim = 192;
constexpr int NHEAD = 6, HDIM = 32, BATCH = 16;
constexpr int BL = BATCH * Lseq;              // 50176 rows
constexpr float LN_EPS = 1e-5f;

// Scratch (device globals: allocation-free, graph-capture safe)
__device__ __align__(16) __nv_bfloat16 g_xnb [(size_t)BL * Cdim];
__device__ __align__(16) __nv_bfloat16 g_h0b [(size_t)BL * Cdim];
__device__ __align__(16) __nv_bfloat16 g_actb[(size_t)BL * Cdim];
__device__ __align__(16) __nv_bfloat16 g_hb  [(size_t)BL * Cdim];
__device__ __align__(16) __nv_bfloat16 g_qkb [(size_t)BL * 2 * Cdim];
__device__ __align__(16) __nv_bfloat16 g_gb  [(size_t)BL * Cdim];
__device__ __align__(16) float g_att[(size_t)BL * Cdim];
__device__ __align__(16) float g_kv [BATCH * NHEAD * HDIM * HDIM];
__device__ __align__(16) float g_km [BATCH * NHEAD * HDIM];
// bf16 weights
__device__ __align__(16) __nv_bfloat16 g_wcat[Cdim * 2 * Cdim];   // in_w | act_w
__device__ __align__(16) __nv_bfloat16 g_qkw [Cdim * 2 * Cdim];
__device__ __align__(16) __nv_bfloat16 g_outw[Cdim * Cdim];

// ---------------------------------------------------------------------------
// helpers
// ---------------------------------------------------------------------------
__device__ __forceinline__ uint32_t smem_u32(const void* p) {
    return (uint32_t)__cvta_generic_to_shared(p);
}
__device__ __forceinline__ void ldm_x4(uint32_t& r0, uint32_t& r1, uint32_t& r2,
                                       uint32_t& r3, uint32_t a) {
    asm volatile("ldmatrix.sync.aligned.m8n8.x4.shared.b16 {%0,%1,%2,%3}, [%4];"
                 : "=r"(r0), "=r"(r1), "=r"(r2), "=r"(r3) : "r"(a));
}
__device__ __forceinline__ void ldm_x4t(uint32_t& r0, uint32_t& r1, uint32_t& r2,
                                        uint32_t& r3, uint32_t a) {
    asm volatile("ldmatrix.sync.aligned.m8n8.x4.trans.shared.b16 {%0,%1,%2,%3}, [%4];"
                 : "=r"(r0), "=r"(r1), "=r"(r2), "=r"(r3) : "r"(a));
}
__device__ __forceinline__ void mma16816(float* c, uint32_t a0, uint32_t a1,
                                         uint32_t a2, uint32_t a3,
                                         uint32_t b0, uint32_t b1) {
    asm volatile(
        "mma.sync.aligned.m16n8k16.row.col.f32.bf16.bf16.f32 "
        "{%0,%1,%2,%3}, {%4,%5,%6,%7}, {%8,%9}, {%0,%1,%2,%3};"
        : "+f"(c[0]), "+f"(c[1]), "+f"(c[2]), "+f"(c[3])
        : "r"(a0), "r"(a1), "r"(a2), "r"(a3), "r"(b0), "r"(b1));
}
__device__ __forceinline__ void cpa16(uint32_t dst, const void* src) {
    asm volatile("cp.async.cg.shared.global [%0], [%1], 16;" :: "r"(dst), "l"(src));
}
__device__ __forceinline__ __nv_bfloat162 pack2(float a, float b) {
    return __floats2bfloat162_rn(a, b);
}

// ---------------------------------------------------------------------------
// weight conversion (runs each launch; ~2us)
// ---------------------------------------------------------------------------
__global__ void convw_kernel(const float* __restrict__ in_w, const float* __restrict__ act_w,
                             const float* __restrict__ qk_w, const float* __restrict__ out_w)
{
    int i = blockIdx.x * 256 + threadIdx.x;
    if (i < Cdim * 2 * Cdim) {
        int r = i / (2 * Cdim), c = i % (2 * Cdim);
        float v = (c < Cdim) ? in_w[r * Cdim + c] : act_w[r * Cdim + (c - Cdim)];
        g_wcat[i] = __float2bfloat16(v);
        g_qkw[i]  = __float2bfloat16(qk_w[i]);
    }
    if (i < Cdim * Cdim) g_outw[i] = __float2bfloat16(out_w[i]);
}

// ---------------------------------------------------------------------------
// LayerNorm -> bf16: one warp per row of 192
// ---------------------------------------------------------------------------
__global__ void ln_kernel(const float* __restrict__ x, const float* __restrict__ gamma,
                          const float* __restrict__ beta, __nv_bfloat16* __restrict__ out) {
    int row  = blockIdx.x * 8 + (threadIdx.x >> 5);
    int lane = threadIdx.x & 31;
    const float* xr = x + (size_t)row * Cdim;
    float v[6]; float s = 0.f, ss = 0.f;
#pragma unroll
    for (int i = 0; i < 6; i++) { v[i] = xr[lane + 32 * i]; s += v[i]; ss += v[i] * v[i]; }
#pragma unroll
    for (int o = 16; o > 0; o >>= 1) {
        s  += __shfl_xor_sync(0xffffffffu, s,  o);
        ss += __shfl_xor_sync(0xffffffffu, ss, o);
    }
    float mu   = s * (1.f / Cdim);
    float var  = ss * (1.f / Cdim) - mu * mu;
    float rstd = rsqrtf(var + LN_EPS);
    __nv_bfloat16* orow = out + (size_t)row * Cdim;
#pragma unroll
    for (int i = 0; i < 6; i++) {
        int c = lane + 32 * i;
        orow[c] = __float2bfloat16((v[i] - mu) * rstd * gamma[c] + beta[c]);
    }
}

// ---------------------------------------------------------------------------
// bf16 GEMM with cp.async double buffering.
// BM=128, BN=64, BK=32, 8 warps (4x2), warp tile 32x32 via m16n8k16.
// MODE 0: split output (cols<192 -> Y1 no-act; cols>=192 -> Y2 silu), stride 192
// MODE 1: elu+1 -> Y1 (bf16, stride N)
// MODE 2: none + resid(fp32) -> Yf (fp32, stride N)
// ---------------------------------------------------------------------------
template <int MODE>
__global__ __launch_bounds__(256) void gemm2(
    const __nv_bfloat16* __restrict__ A, const __nv_bfloat16* __restrict__ W,
    const float* __restrict__ bias1, const float* __restrict__ bias2,
    const float* __restrict__ resid,
    __nv_bfloat16* __restrict__ Y1, __nv_bfloat16* __restrict__ Y2,
    float* __restrict__ Yf, int M, int N, int K)
{
    constexpr int BM = 128, BN = 64, BK = 32;
    constexpr int ASTR = 40;   // bf16 elems per A smem row (80B = 5x16B, conflict-free)
    constexpr int BSTR = 72;   // bf16 elems per B smem row (144B = 9x16B)
    constexpr int ASTAGE = BM * ASTR;   // elems
    constexpr int BSTAGE = BK * BSTR;
    __shared__ __align__(16) __nv_bfloat16 As[2 * ASTAGE];  // 20480 B
    __shared__ __align__(16) __nv_bfloat16 Bs[2 * BSTAGE];  //  9216 B

    int tid  = threadIdx.x;
    int bm   = blockIdx.y * BM, bn = blockIdx.x * BN;
    int warp = tid >> 5, lane = tid & 31;
    int wm   = (warp & 3) * 32, wn = (warp >> 2) * 32;

    uint32_t as_base = smem_u32(As);
    uint32_t bs_base = smem_u32(Bs);

    float acc[2][4][4];
#pragma unroll
    for (int i = 0; i < 2; i++)
#pragma unroll
        for (int j = 0; j < 4; j++)
#pragma unroll
            for (int l = 0; l < 4; l++) acc[i][j][l] = 0.f;

    int a_row = wm + (lane & 7) + ((lane >> 3) & 1) * 8;
    int a_col = (lane >> 4) * 8;
    int b_k   = (lane & 7) + ((lane >> 3) & 1) * 8;
    int b_n   = wn + (lane >> 4) * 8;

    // async loader: stage in {0,1}
    auto load_stage = [&](int stage, int kt) {
        uint32_t ab = as_base + stage * ASTAGE * 2;
#pragma unroll
        for (int i = 0; i < 2; i++) {
            int idx = i * 256 + tid;            // 512 chunks of 16B
            int r = idx >> 2, c = idx & 3;      // 128 rows x 4 chunks
            cpa16(ab + (r * ASTR + c * 8) * 2,
                  A + (size_t)(bm + r) * K + kt * BK + c * 8);
        }
        uint32_t bb = bs_base + stage * BSTAGE * 2;
        {
            int r = tid >> 3, c = tid & 7;      // 32 rows x 8 chunks
            cpa16(bb + (r * BSTR + c * 8) * 2,
                  W + (size_t)(kt * BK + r) * N + bn + c * 8);
        }
        asm volatile("cp.async.commit_group;" ::: "memory");
    };

    const int KT = K / BK;
    load_stage(0, 0);
    for (int kt = 0; kt < KT; kt++) {
        if (kt + 1 < KT) {
            load_stage((kt + 1) & 1, kt + 1);
            asm volatile("cp.async.wait_group 1;" ::: "memory");
        } else {
            asm volatile("cp.async.wait_group 0;" ::: "memory");
        }
        __syncthreads();
        uint32_t ab = as_base + (kt & 1) * ASTAGE * 2;
        uint32_t bb = bs_base + (kt & 1) * BSTAGE * 2;
#pragma unroll
        for (int ks = 0; ks < 2; ks++) {
            uint32_t afr[2][4];
#pragma unroll
            for (int mt = 0; mt < 2; mt++) {
                uint32_t addr = ab + ((a_row + mt * 16) * ASTR + (a_col + ks * 16)) * 2;
                ldm_x4(afr[mt][0], afr[mt][1], afr[mt][2], afr[mt][3], addr);
            }
            uint32_t bfr[4][2];
#pragma unroll
            for (int p = 0; p < 2; p++) {
                uint32_t addr = bb + ((b_k + ks * 16) * BSTR + (b_n + p * 16)) * 2;
                uint32_t r0, r1, r2, r3;
                ldm_x4t(r0, r1, r2, r3, addr);
                bfr[p * 2 + 0][0] = r0; bfr[p * 2 + 0][1] = r1;
                bfr[p * 2 + 1][0] = r2; bfr[p * 2 + 1][1] = r3;
            }
#pragma unroll
            for (int mt = 0; mt < 2; mt++)
#pragma unroll
                for (int nt = 0; nt < 4; nt++)
                    mma16816(acc[mt][nt], afr[mt][0], afr[mt][1], afr[mt][2],
                             afr[mt][3], bfr[nt][0], bfr[nt][1]);
        }
        __syncthreads();
    }

    // epilogue
    int r0 = lane >> 2, c0 = (lane & 3) * 2;
    bool first = (bn < Cdim);                 // MODE 0 split (uniform per block)
#pragma unroll
    for (int mt = 0; mt < 2; mt++) {
#pragma unroll
        for (int half = 0; half < 2; half++) {
            int row = bm + wm + mt * 16 + r0 + half * 8;
#pragma unroll
            for (int nt = 0; nt < 4; nt++) {
                int col = bn + wn + nt * 8 + c0;
                float v0 = acc[mt][nt][half * 2 + 0];
                float v1 = acc[mt][nt][half * 2 + 1];
                if (MODE == 0) {
                    int cl = first ? col : col - Cdim;
                    const float* bs = first ? bias1 : bias2;
                    v0 += bs[cl]; v1 += bs[cl + 1];
                    if (!first) {
                        v0 = v0 / (1.f + expf(-v0));
                        v1 = v1 / (1.f + expf(-v1));
                    }
                    __nv_bfloat16* dst = first ? Y1 : Y2;
                    *(__nv_bfloat162*)&dst[(size_t)row * Cdim + cl] = pack2(v0, v1);
                } else if (MODE == 1) {
                    v0 += bias1[col]; v1 += bias1[col + 1];
                    v0 = (v0 > 0.f) ? v0 + 1.f : expf(v0);
                    v1 = (v1 > 0.f) ? v1 + 1.f : expf(v1);
                    *(__nv_bfloat162*)&Y1[(size_t)row * N + col] = pack2(v0, v1);
                } else {
                    v0 += bias1[col]; v1 += bias1[col + 1];
                    float2 rr = *(const float2*)&resid[(size_t)row * N + col];
                    v0 += rr.x; v1 += rr.y;
                    float2 o; o.x = v0; o.y = v1;
                    *(float2*)&Yf[(size_t)row * N + col] = o;
                }
            }
        }
    }
}

// ---------------------------------------------------------------------------
// Depthwise 3x3 SAME conv + silu, bf16x2: 96 threads (2ch each), 4 rows/thread
// ---------------------------------------------------------------------------
__global__ void dwconv_silu_kernel(const __nv_bfloat162* __restrict__ in,
                                   const float* __restrict__ w,
                                   const float* __restrict__ bias,
                                   __nv_bfloat162* __restrict__ out)
{
    int blk = blockIdx.x;
    int c2  = threadIdx.x;              // 0..95
    int x   = blk % Wimg;
    int t   = blk / Wimg;
    int y4  = t % (Himg / 4);
    int b   = t / (Himg / 4);
    int y0  = y4 * 4;

    float2 wv[9];
#pragma unroll
    for (int i = 0; i < 9; i++) wv[i] = *(const float2*)&w[i * Cdim + 2 * c2];
    float2 bb = *(const float2*)&bias[2 * c2];
    float2 acc[4];
#pragma unroll
    for (int i = 0; i < 4; i++) acc[i] = bb;

#pragma unroll
    for (int dx = 0; dx < 3; dx++) {
        int xx = x + dx - 1;
        if (xx < 0 || xx >= Wimg) continue;
#pragma unroll
        for (int ry = -1; ry < 5; ry++) {
            int yy = y0 + ry;
            if (yy < 0 || yy >= Himg) continue;
            __nv_bfloat162 raw = in[((size_t)(b * Himg + yy) * Wimg + xx) * 96 + c2];
            float2 v = __bfloat1622float2(raw);
#pragma unroll
            for (int oy = 0; oy < 4; oy++) {
                int dy = ry - oy + 1;
                if (dy >= 0 && dy < 3) {
                    acc[oy].x = fmaf(v.x, wv[dy * 3 + dx].x, acc[oy].x);
                    acc[oy].y = fmaf(v.y, wv[dy * 3 + dx].y, acc[oy].y);
                }
            }
        }
    }
#pragma unroll
    for (int oy = 0; oy < 4; oy++) {
        float a0 = acc[oy].x, a1 = acc[oy].y;
        a0 = a0 / (1.f + expf(-a0));
        a1 = a1 / (1.f + expf(-a1));
        out[((size_t)(b * Himg + y0 + oy) * Wimg + x) * 96 + c2] = pack2(a0, a1);
    }
}

// Fused: g = (att + dwconv(h)+lepe_b) * act_res
__global__ void lepe_mul_kernel(const __nv_bfloat162* __restrict__ hin,
                                const float* __restrict__ w,
                                const float* __restrict__ bias,
                                const float* __restrict__ att,
                                const __nv_bfloat162* __restrict__ actres,
                                __nv_bfloat162* __restrict__ out)
{
    int blk = blockIdx.x;
    int c2  = threadIdx.x;
    int x   = blk % Wimg;
    int t   = blk / Wimg;
    int y4  = t % (Himg / 4);
    int b   = t / (Himg / 4);
    int y0  = y4 * 4;

    float2 wv[9];
#pragma unroll
    for (int i = 0; i < 9; i++) wv[i] = *(const float2*)&w[i * Cdim + 2 * c2];
    float2 bb = *(const float2*)&bias[2 * c2];
    float2 acc[4];
#pragma unroll
    for (int i = 0; i < 4; i++) acc[i] = bb;

#pragma unroll
    for (int dx = 0; dx < 3; dx++) {
        int xx = x + dx - 1;
        if (xx < 0 || xx >= Wimg) continue;
#pragma unroll
        for (int ry = -1; ry < 5; ry++) {
            int yy = y0 + ry;
            if (yy < 0 || yy >= Himg) continue;
            float2 v = __bfloat1622float2(hin[((size_t)(b * Himg + yy) * Wimg + xx) * 96 + c2]);
#pragma unroll
            for (int oy = 0; oy < 4; oy++) {
                int dy = ry - oy + 1;
                if (dy >= 0 && dy < 3) {
                    acc[oy].x = fmaf(v.x, wv[dy * 3 + dx].x, acc[oy].x);
                    acc[oy].y = fmaf(v.y, wv[dy * 3 + dx].y, acc[oy].y);
                }
            }
        }
    }
#pragma unroll
    for (int oy = 0; oy < 4; oy++) {
        size_t pix = (size_t)(b * Himg + y0 + oy) * Wimg + x;
        float2 at = *(const float2*)&att[pix * Cdim + 2 * c2];
        float2 ar = __bfloat1622float2(actres[pix * 96 + c2]);
        out[pix * 96 + c2] = pack2((at.x + acc[oy].x) * ar.x,
                                   (at.y + acc[oy].y) * ar.y);
    }
}

// ---------------------------------------------------------------------------
// kv[b,h] = k^T v / L  (32x32), kmean = mean_n k
// ---------------------------------------------------------------------------
__global__ void kv_kernel(const __nv_bfloat16* __restrict__ qk,
                          const __nv_bfloat16* __restrict__ hv,
                          float* __restrict__ kv, float* __restrict__ km)
{
    int bh = blockIdx.x;
    int b = bh / NHEAD, hd = bh % NHEAD;
    __shared__ float skv[HDIM * HDIM];
    __shared__ float skm[HDIM];
    int tid = threadIdx.x;
    for (int i = tid; i < HDIM * HDIM; i += blockDim.x) skv[i] = 0.f;
    if (tid < HDIM) skm[tid] = 0.f;
    __syncthreads();

    int lane = tid & 31, warp = tid >> 5;
    float acc[HDIM];
#pragma unroll
    for (int e = 0; e < HDIM; e++) acc[e] = 0.f;
    float acck = 0.f;

    for (int n = warp; n < Lseq; n += 8) {
        size_t rowq = (size_t)(b * Lseq + n) * (2 * Cdim);
        float kd = __bfloat162float(qk[rowq + Cdim + hd * HDIM + lane]);
        float ve = __bfloat162float(hv[(size_t)(b * Lseq + n) * Cdim + hd * HDIM + lane]);
        acck += kd;
#pragma unroll
        for (int e = 0; e < HDIM; e++)
            acc[e] = fmaf(kd, __shfl_sync(0xffffffffu, ve, e), acc[e]);
    }
#pragma unroll
    for (int e = 0; e < HDIM; e++) atomicAdd(&skv[lane * HDIM + e], acc[e]);
    atomicAdd(&skm[lane], acck);
    __syncthreads();

    const float invL = 1.f / (float)Lseq;
    for (int i = tid; i < HDIM * HDIM; i += blockDim.x)
        kv[(size_t)bh * HDIM * HDIM + i] = skv[i] * invL;
    if (tid < HDIM) km[bh * HDIM + tid] = skm[tid] * invL;
}

// ---------------------------------------------------------------------------
// att[n, h*32+e] = z * sum_d q[n,d]*kv[d,e];  z = 1/(q.kmean + 1e-6)
// ---------------------------------------------------------------------------
__global__ void att_kernel(const __nv_bfloat16* __restrict__ qk,
                           const float* __restrict__ kv,
                           const float* __restrict__ km, float* __restrict__ att)
{
    int bh = blockIdx.x;
    int b = bh / NHEAD, hd = bh % NHEAD;
    __shared__ float skv[HDIM * HDIM];
    __shared__ float skm[HDIM];
    int tid = threadIdx.x;
    for (int i = tid; i < HDIM * HDIM; i += blockDim.x)
        skv[i] = kv[(size_t)bh * HDIM * HDIM + i];
    if (tid < HDIM) skm[tid] = km[bh * HDIM + tid];
    __syncthreads();

    int lane = tid & 31, warp = tid >> 5;
    const int per = Lseq / 8;
    int n0 = blockIdx.y * per;
    for (int n = n0 + warp; n < n0 + per; n += 8) {
        float qe = __bfloat162float(qk[(size_t)(b * Lseq + n) * (2 * Cdim) + hd * HDIM + lane]);
        float p = qe * skm[lane];
#pragma unroll
        for (int o = 16; o > 0; o >>= 1) p += __shfl_xor_sync(0xffffffffu, p, o);
        float z = 1.f / (p + 1e-6f);
        float a = 0.f;
#pragma unroll
        for (int d = 0; d < HDIM; d++)
            a = fmaf(__shfl_sync(0xffffffffu, qe, d), skv[d * HDIM + lane], a);
        att[(size_t)(b * Lseq + n) * Cdim + hd * HDIM + lane] = a * z;
    }
}

// ---------------------------------------------------------------------------
extern "C" void kernel_launch(void* const* d_in, const int* in_sizes, int n_in,
                              void* d_out, int out_size)
{
    const float* x      = (const float*)d_in[0];
    const float* norm_g = (const float*)d_in[1];
    const float* norm_b = (const float*)d_in[2];
    const float* in_w   = (const float*)d_in[3];
    const float* in_b   = (const float*)d_in[4];
    const float* act_w  = (const float*)d_in[5];
    const float* act_b  = (const float*)d_in[6];
    const float* dwc_w  = (const float*)d_in[7];
    const float* dwc_b  = (const float*)d_in[8];
    const float* qk_w   = (const float*)d_in[9];
    const float* qk_b   = (const float*)d_in[10];
    const float* lepe_w = (const float*)d_in[11];
    const float* lepe_b = (const float*)d_in[12];
    const float* out_w  = (const float*)d_in[13];
    const float* out_b  = (const float*)d_in[14];
    float* out = (float*)d_out;

    __nv_bfloat16 *xnb, *h0b, *actb, *hb, *qkb, *gb, *wcat, *qkw, *outw;
    float *att, *kv, *km;
    cudaGetSymbolAddress((void**)&xnb,  g_xnb);
    cudaGetSymbolAddress((void**)&h0b,  g_h0b);
    cudaGetSymbolAddress((void**)&actb, g_actb);
    cudaGetSymbolAddress((void**)&hb,   g_hb);
    cudaGetSymbolAddress((void**)&qkb,  g_qkb);
    cudaGetSymbolAddress((void**)&gb,   g_gb);
    cudaGetSymbolAddress((void**)&att,  g_att);
    cudaGetSymbolAddress((void**)&kv,   g_kv);
    cudaGetSymbolAddress((void**)&km,   g_km);
    cudaGetSymbolAddress((void**)&wcat, g_wcat);
    cudaGetSymbolAddress((void**)&qkw,  g_qkw);
    cudaGetSymbolAddress((void**)&outw, g_outw);

    // 0) convert weights to bf16 (+ concat in_w|act_w)
    convw_kernel<<<(Cdim * 2 * Cdim + 255) / 256, 256>>>(in_w, act_w, qk_w, out_w);

    // 1) LayerNorm -> bf16
    ln_kernel<<<BL / 8, 256>>>(x, norm_g, norm_b, xnb);

    // 2) fused in-proj + act-proj GEMM (N=384, split epilogue)
    gemm2<0><<<dim3(6, BL / 128), 256>>>(xnb, wcat, in_b, act_b, nullptr,
                                         h0b, actb, nullptr, BL, 2 * Cdim, Cdim);

    // 3) dwconv + silu -> h
    int dwgrid = BATCH * (Himg / 4) * Wimg;
    dwconv_silu_kernel<<<dwgrid, 96>>>((const __nv_bfloat162*)h0b, dwc_w, dwc_b,
                                       (__nv_bfloat162*)hb);

    // 4) qk-proj with elu+1
    gemm2<1><<<dim3(6, BL / 128), 256>>>(hb, qkw, qk_b, nullptr, nullptr,
                                         qkb, nullptr, nullptr, BL, 2 * Cdim, Cdim);

    // 5) linear attention
    kv_kernel<<<BATCH * NHEAD, 256>>>(qkb, hb, kv, km);
    att_kernel<<<dim3(BATCH * NHEAD, 8), 256>>>(qkb, kv, km, att);

    // 6) g = (att + lepe) * act_res -> gb
    lepe_mul_kernel<<<dwgrid, 96>>>((const __nv_bfloat162*)hb, lepe_w, lepe_b, att,
                                    (const __nv_bfloat162*)actb, (__nv_bfloat162*)gb);

    // 7) out-proj + bias + shortcut -> fp32 out
    gemm2<2><<<dim3(3, BL / 128), 256>>>(gb, outw, out_b, nullptr, x,
                                         nullptr, nullptr, out, BL, Cdim, Cdim);
}